// round 7
// baseline (speedup 1.0000x reference)
#include <cuda_runtime.h>
#include <math.h>
#include <float.h>
#include <stdint.h>

// ---------------- problem constants ----------------
#define BB     4
#define CIN    256
#define HH     200
#define WW     176
#define HWTOT  (HH*WW)          // 35200
#define AA     6
#define NCLS   4
#define NREG   7
#define NOUT   66               // 24 cls + 42 reg
#define NPAD   72               // padded N (9 n-tiles of 8)
#define NANCH  (AA*HWTOT)       // 211200
#define KTOP   100
#define BOXSTRIDE 8

// ---------------- tiling ----------------
#define TILE_M     128
#define TILES_PER_B (HWTOT/TILE_M)   // 275 exact
#define TILES_TOTAL (TILES_PER_B*BB) // 1100
#define KCHUNK     64
#define NCHUNKS    (CIN/KCHUNK)      // 4
#define GRID_HEAD  148
#define NTHREADS   256               // 8 warps, each owns a 16-row M strip
#define NT_TILES   (NPAD/8)          // 9

// ---------------- smem layout ----------------
#define XS_STRIDE  136               // 128 + 8 pad: conflict-free a-frag LDS
#define XS_BYTES   (KCHUNK*XS_STRIDE*4)   // 34816
#define ESTRIDE    76                // epilogue tile stride (72 + 4 pad)
#define SM_WH      0                 // weight hi: [256][72] tf32  (73728 B)
#define SM_WL      73728             // weight lo
#define SM_XS0     147456
#define SM_XS1     (SM_XS0 + XS_BYTES)    // 182272
#define SM_BIAS    (SM_XS1 + XS_BYTES)    // 217088
#define SM_TOTAL   (SM_BIAS + NPAD*4)     // 217376

// ---------------- top-k constants ----------------
#define NBINS   65536
#define CANDMAX 4096

// ---------------- device scratch ----------------
__device__ float    g_scores[(size_t)BB*NANCH*NCLS];
__device__ float    g_boxes [(size_t)BB*NANCH*BOXSTRIDE];
__device__ float    g_maxs  [(size_t)BB*NANCH];
__device__ unsigned g_hist  [BB*NBINS];

// ---------------- helpers ----------------
__device__ __forceinline__ uint32_t f2tf32(float f) {   // round-to-nearest tf32 bits
    uint32_t u;
    asm("cvt.rna.tf32.f32 %0, %1;" : "=r"(u) : "f"(f));
    return u;
}
__device__ __forceinline__ void cp16(uint32_t smem_addr, const void* gptr) {
    asm volatile("cp.async.ca.shared.global [%0], [%1], 16;"
                 :: "r"(smem_addr), "l"(gptr));
}
__device__ __forceinline__ void cp_commit() {
    asm volatile("cp.async.commit_group;");
}
template<int N> __device__ __forceinline__ void cp_wait() {
    asm volatile("cp.async.wait_group %0;" :: "n"(N));
}
// m16n8k8 tf32 MMA (sm_80+ base-target legal; HMMA on the tensor pipe)
__device__ __forceinline__ void mma8(float d[4], const uint32_t a[4],
                                     uint32_t b0, uint32_t b1) {
    asm volatile("mma.sync.aligned.m16n8k8.row.col.f32.tf32.tf32.f32 "
                 "{%0,%1,%2,%3}, {%4,%5,%6,%7}, {%8,%9}, {%0,%1,%2,%3};"
                 : "+f"(d[0]), "+f"(d[1]), "+f"(d[2]), "+f"(d[3])
                 : "r"(a[0]), "r"(a[1]), "r"(a[2]), "r"(a[3]),
                   "r"(b0), "r"(b1));
}

// ============================================================================
// Stage 0: zero the histogram
// ============================================================================
__global__ void zero_kernel() {
    int i = blockIdx.x*blockDim.x + threadIdx.x;
    if (i < BB*NBINS/4) ((uint4*)g_hist)[i] = make_uint4(0u,0u,0u,0u);
}

// ============================================================================
// Stage 1: persistent tf32-MMA head (3xTF32 split, fp32-grade accuracy)
// ============================================================================
__global__ __launch_bounds__(NTHREADS)
void head_kernel(const float* __restrict__ x,
                 const float* __restrict__ cls_w, const float* __restrict__ cls_b,
                 const float* __restrict__ reg_w, const float* __restrict__ reg_b,
                 const float* __restrict__ anchors)
{
    extern __shared__ char smem[];
    uint32_t* wh   = (uint32_t*)(smem + SM_WH);
    uint32_t* wl   = (uint32_t*)(smem + SM_WL);
    float*    xs0  = (float*)(smem + SM_XS0);
    float*    xs1  = (float*)(smem + SM_XS1);
    float*    esm  = (float*)(smem + SM_XS0);   // overlays xs buffers post-GEMM
    float*    sbias= (float*)(smem + SM_BIAS);

    const int tid  = threadIdx.x;
    const int lane = tid & 31;
    const int wrp  = tid >> 5;        // 0..7
    const int gid  = lane >> 2;       // 0..7
    const int tig  = lane & 3;        // 0..3
    const int strip = wrp * 16;       // M strip for this warp

    // ---- one-time: weights -> tf32 hi/lo smem [k][72] ----
    for (int idx = tid; idx < NPAD*CIN; idx += NTHREADS) {
        int n = idx >> 8;            // output channel (0..71)
        int k = idx & 255;
        float v = 0.f;
        if (n < NCLS*AA)   v = cls_w[n*CIN + k];
        else if (n < NOUT) v = reg_w[(n - NCLS*AA)*CIN + k];
        uint32_t h = f2tf32(v);
        wh[k*NPAD + n] = h;
        wl[k*NPAD + n] = f2tf32(v - __uint_as_float(h));
    }
    if (tid < NPAD)
        sbias[tid] = (tid < NCLS*AA) ? cls_b[tid]
                   : (tid < NOUT)    ? reg_b[tid - NCLS*AA] : 0.f;
    __syncthreads();

    for (int tile = blockIdx.x; tile < TILES_TOTAL; tile += GRID_HEAD) {
        const int b   = tile / TILES_PER_B;
        const int hw0 = (tile % TILES_PER_B) * TILE_M;
        const float* xb = x + (size_t)b * CIN * HWTOT;

        float acc[NT_TILES][4];
        #pragma unroll
        for (int nt = 0; nt < NT_TILES; nt++)
            #pragma unroll
            for (int i = 0; i < 4; i++) acc[nt][i] = 0.f;

        // issue async copy of K-chunk into a buffer (raw fp32, [k][m] stride 136)
        auto issue_chunk = [&](int chunk, float* dst) {
            uint32_t ds;
            asm("{ .reg .u64 t; cvta.to.shared.u64 t, %1; cvt.u32.u64 %0, t; }"
                : "=r"(ds) : "l"(dst));
            const float* src = xb + (size_t)(chunk*KCHUNK)*HWTOT + hw0;
            for (int idx = tid; idx < KCHUNK*32; idx += NTHREADS) {  // 2048 cp16
                int k = idx >> 5, u = idx & 31;
                cp16(ds + (uint32_t)(k*XS_STRIDE + u*4)*4u,
                     src + (size_t)k*HWTOT + u*4);
            }
            cp_commit();
        };

        issue_chunk(0, xs0);

        #pragma unroll 1
        for (int it = 0; it < NCHUNKS; it++) {
            float* cur = (it & 1) ? xs1 : xs0;
            if (it + 1 < NCHUNKS) {
                if (it > 0) __syncthreads();   // other buffer fully consumed
                issue_chunk(it + 1, (it & 1) ? xs0 : xs1);
                cp_wait<1>();
            } else {
                cp_wait<0>();
            }
            __syncthreads();

            const int kb = it * KCHUNK;
            #pragma unroll 4
            for (int kk = 0; kk < KCHUNK; kk += 8) {
                // A fragment (raw fp32 from smem, conflict-free), split hi/lo
                const float* xr = cur + (kk + tig)*XS_STRIDE + strip + gid;
                float r0 = xr[0];
                float r1 = xr[8];
                float r2 = xr[4*XS_STRIDE];
                float r3 = xr[4*XS_STRIDE + 8];
                uint32_t ah[4], al[4];
                ah[0] = f2tf32(r0); al[0] = f2tf32(r0 - __uint_as_float(ah[0]));
                ah[1] = f2tf32(r1); al[1] = f2tf32(r1 - __uint_as_float(ah[1]));
                ah[2] = f2tf32(r2); al[2] = f2tf32(r2 - __uint_as_float(ah[2]));
                ah[3] = f2tf32(r3); al[3] = f2tf32(r3 - __uint_as_float(ah[3]));

                const uint32_t* whp = wh + (kb + kk + tig)*NPAD + gid;
                const uint32_t* wlp = wl + (kb + kk + tig)*NPAD + gid;
                #pragma unroll
                for (int nt = 0; nt < NT_TILES; nt++) {
                    uint32_t bh0 = whp[nt*8], bh1 = whp[4*NPAD + nt*8];
                    uint32_t bl0 = wlp[nt*8], bl1 = wlp[4*NPAD + nt*8];
                    mma8(acc[nt], ah, bh0, bh1);   // hi*hi
                    mma8(acc[nt], ah, bl0, bl1);   // hi*lo
                    mma8(acc[nt], al, bh0, bh1);   // lo*hi
                }
            }
        }

        __syncthreads();   // all MMA smem reads done; esm overlays xs buffers

        // ---- scatter D fragments into epilogue tile esm[m][72] ----
        {
            const int r0 = strip + gid, r1 = r0 + 8;
            #pragma unroll
            for (int nt = 0; nt < NT_TILES; nt++) {
                int c = nt*8 + tig*2;
                *(float2*)&esm[r0*ESTRIDE + c] = make_float2(acc[nt][0], acc[nt][1]);
                *(float2*)&esm[r1*ESTRIDE + c] = make_float2(acc[nt][2], acc[nt][3]);
            }
        }
        __syncthreads();

        // ---- per-anchor epilogue: one thread per hw row ----
        if (tid < TILE_M) {
            const float* e = esm + tid*ESTRIDE;
            float dv[NOUT];
            #pragma unroll
            for (int o = 0; o < NOUT; o++) dv[o] = e[o] + sbias[o];

            const int hw = hw0 + tid;
            #pragma unroll
            for (int a = 0; a < AA; a++) {
                const int n = hw*AA + a;
                // softmax over 4 class logits
                float l0 = dv[a*4+0], l1 = dv[a*4+1], l2 = dv[a*4+2], l3 = dv[a*4+3];
                float mm = fmaxf(fmaxf(l0, l1), fmaxf(l2, l3));
                float e0 = expf(l0-mm), e1 = expf(l1-mm), e2 = expf(l2-mm), e3 = expf(l3-mm);
                float inv = 1.f / (e0 + e1 + e2 + e3);
                float p0 = e0*inv, p1 = e1*inv, p2 = e2*inv, p3 = e3*inv;

                const size_t base = (size_t)b*NANCH + n;
                *(float4*)(g_scores + base*4) = make_float4(p0, p1, p2, p3);
                float mx = fmaxf(fmaxf(p1, p2), p3);
                g_maxs[base] = mx;

                unsigned bin   = __float_as_uint(mx) >> 16;
                unsigned amask = __activemask();
                unsigned peers = __match_any_sync(amask, bin);
                int leader = __ffs(peers) - 1;
                if (lane == leader)
                    atomicAdd(&g_hist[b*NBINS + bin], (unsigned)__popc(peers));

                // decode
                const float* an = anchors + (size_t)n*NREG;
                float xa = an[0], ya = an[1], za = an[2];
                float dxa = an[3], dya = an[4], dza = an[5], ra = an[6];
                float diag = sqrtf(dxa*dxa + dya*dya);
                const float* d = dv + NCLS*AA + a*NREG;
                float4 b0, b1;
                b0.x = fmaf(d[0], diag, xa);
                b0.y = fmaf(d[1], diag, ya);
                b0.z = fmaf(d[2], dza,  za);
                b0.w = expf(d[3]) * dxa;
                b1.x = expf(d[4]) * dya;
                b1.y = expf(d[5]) * dza;
                b1.z = d[6] + ra;
                b1.w = 0.f;
                float* ob = g_boxes + base*BOXSTRIDE;
                *(float4*)(ob + 0) = b0;
                *(float4*)(ob + 4) = b1;
            }
        }
        __syncthreads();   // esm reads done before next tile's prefetch
    }
}

// ============================================================================
// Stage 2: per-batch fused threshold-find + compact + sort + gather
// ============================================================================
__global__ __launch_bounds__(1024)
void select_kernel(float* __restrict__ outS, float* __restrict__ outB)
{
    const int b   = blockIdx.x;
    const int tid = threadIdx.x;
    const int lane = tid & 31;
    const int wrp  = tid >> 5;

    __shared__ unsigned csum[1024];
    __shared__ unsigned wsum[32];
    __shared__ int      sThr;
    __shared__ int      sCnt;
    __shared__ float    sv[CANDMAX];
    __shared__ int      si[CANDMAX];

    const unsigned* h = g_hist + b*NBINS;
    {
        const uint4* h4 = (const uint4*)(h + tid*64);
        unsigned s = 0;
        #pragma unroll
        for (int k = 0; k < 16; k++) { uint4 v = h4[k]; s += v.x + v.y + v.z + v.w; }
        csum[tid] = s;
        unsigned ws = s;
        #pragma unroll
        for (int o = 16; o > 0; o >>= 1) ws += __shfl_down_sync(0xFFFFFFFFu, ws, o);
        if (lane == 0) wsum[wrp] = ws;
    }
    if (tid == 0) sCnt = 0;
    __syncthreads();

    if (tid == 0) {
        unsigned cum = 0;
        int w = 31;
        for (; w > 0; w--) { if (cum + wsum[w] >= (unsigned)KTOP) break; cum += wsum[w]; }
        int t = w*32 + 31;
        for (; t > w*32; t--) { if (cum + csum[t] >= (unsigned)KTOP) break; cum += csum[t]; }
        int thr = t*64;
        for (int k = 63; k >= 0; k--) {
            unsigned c = h[t*64 + k];
            if (cum + c >= (unsigned)KTOP) { thr = t*64 + k; break; }
            cum += c;
        }
        sThr = thr;
    }
    __syncthreads();

    {
        const int thr = sThr;
        const float* mv = g_maxs + (size_t)b*NANCH;
        for (int i = tid; i < NANCH; i += 1024) {
            float v = mv[i];
            if ((int)(__float_as_uint(v) >> 16) >= thr) {
                int p = atomicAdd(&sCnt, 1);
                if (p < CANDMAX) { sv[p] = v; si[p] = i; }
            }
        }
    }
    __syncthreads();

    int cnt = sCnt;
    if (cnt > CANDMAX) cnt = CANDMAX;
    int p2 = 128;
    while (p2 < cnt) p2 <<= 1;
    for (int k = cnt + tid; k < p2; k += 1024) { sv[k] = -FLT_MAX; si[k] = 0x7FFFFFFF; }
    __syncthreads();

    for (int k2 = 2; k2 <= p2; k2 <<= 1) {
        for (int j = k2 >> 1; j > 0; j >>= 1) {
            for (int i = tid; i < p2; i += 1024) {
                int ixj = i ^ j;
                if (ixj > i) {
                    float va = sv[i], vb = sv[ixj];
                    int   ia = si[i], ib = si[ixj];
                    bool a_below_b = (va < vb) || (va == vb && ia > ib);
                    bool up = ((i & k2) == 0);
                    if (up ? a_below_b : !a_below_b) {
                        sv[i] = vb; sv[ixj] = va; si[i] = ib; si[ixj] = ia;
                    }
                }
            }
            __syncthreads();
        }
    }

    if (tid < KTOP) {
        int k = tid;
        int n = si[k];
        size_t base = (size_t)b*NANCH + n;
        float4 s4 = *(const float4*)(g_scores + base*4);
        *(float4*)(outS + ((size_t)b*KTOP + k)*4) = s4;
        const float* bx = g_boxes + base*BOXSTRIDE;
        float4 b0 = *(const float4*)(bx + 0);
        float4 b1 = *(const float4*)(bx + 4);
        float* ob = outB + ((size_t)b*KTOP + k)*NREG;
        ob[0] = b0.x; ob[1] = b0.y; ob[2] = b0.z; ob[3] = b0.w;
        ob[4] = b1.x; ob[5] = b1.y; ob[6] = b1.z;
    }
}

// ============================================================================
extern "C" void kernel_launch(void* const* d_in, const int* in_sizes, int n_in,
                              void* d_out, int out_size)
{
    const float* x       = (const float*)d_in[0];
    const float* cls_w   = (const float*)d_in[1];
    const float* cls_b   = (const float*)d_in[2];
    const float* reg_w   = (const float*)d_in[3];
    const float* reg_b   = (const float*)d_in[4];
    const float* anchors = (const float*)d_in[5];

    float* outS = (float*)d_out;                 // [B, K, 4]
    float* outB = outS + (size_t)BB*KTOP*NCLS;   // [B, K, 7]

    cudaFuncSetAttribute(head_kernel, cudaFuncAttributeMaxDynamicSharedMemorySize,
                         SM_TOTAL);

    zero_kernel<<<(BB*NBINS/4 + 255)/256, 256>>>();
    head_kernel<<<GRID_HEAD, NTHREADS, SM_TOTAL>>>(x, cls_w, cls_b, reg_w, reg_b, anchors);
    select_kernel<<<BB, 1024>>>(outS, outB);
}

// round 12
// speedup vs baseline: 1.1552x; 1.1552x over previous
#include <cuda_runtime.h>
#include <math.h>
#include <float.h>
#include <stdint.h>

// ---------------- problem constants ----------------
#define BB     4
#define CIN    256
#define HH     200
#define WW     176
#define HWTOT  (HH*WW)          // 35200
#define AA     6
#define NCLS   4
#define NREG   7
#define NOUT   (NCLS*AA + NREG*AA)   // 66 (24 cls + 42 reg)
#define NANCH  (AA*HWTOT)       // 211200
#define KTOP   100
#define BOXSTRIDE 8             // padded box row in scratch

// ---------------- stage-1 tiling ----------------
#define TILE_HW  256
#define CK       16
#define NITER    (CIN/CK)       // 16
#define NTHREADS 352            // 11 warps
#define OT       6              // outputs per warp (11*6 = 66)
#define NPAIR    4              // hw PAIRS per thread (32 lanes * 4 pairs * 2 = 256)
#define ESM_STRIDE 67           // padded row stride for epilogue smem
#define WREGION  (TILE_HW*ESM_STRIDE)     // 17152 floats (>= 66*256 = 16896)
#define CHUNK_FLOATS (CK*TILE_HW)         // 4096
#define CHUNK_F4 (CHUNK_FLOATS/4)         // 1024
#define SMEM_FLOATS (WREGION + 2*CHUNK_FLOATS)
#define SMEM_BYTES  (SMEM_FLOATS*4)       // ~101 KB

// ---------------- top-k constants ----------------
#define NBINS   65536
#define CANDMAX 4096

// ---------------- device scratch (static: no allocation allowed) ----------------
__device__ float    g_scores[(size_t)BB*NANCH*NCLS];
__device__ float    g_boxes [(size_t)BB*NANCH*BOXSTRIDE];
__device__ float    g_maxs  [(size_t)BB*NANCH];
__device__ unsigned g_hist  [BB*NBINS];

// ---------------- cp.async helpers ----------------
__device__ __forceinline__ void cp16(uint32_t smem_addr, const void* gptr) {
    asm volatile("cp.async.ca.shared.global [%0], [%1], 16;"
                 :: "r"(smem_addr), "l"(gptr));
}
__device__ __forceinline__ void cp_commit() {
    asm volatile("cp.async.commit_group;");
}
template<int N> __device__ __forceinline__ void cp_wait() {
    asm volatile("cp.async.wait_group %0;" :: "n"(N));
}

// ---------------- packed f32x2 helpers (Blackwell sm_100+ base) ----------------
__device__ __forceinline__ void ffma2(unsigned long long& d,
                                      unsigned long long a,
                                      unsigned long long b) {
    asm("fma.rn.f32x2 %0, %1, %2, %0;" : "+l"(d) : "l"(a), "l"(b));
}
__device__ __forceinline__ unsigned long long pack_dup(float w) {
    unsigned long long r;
    asm("mov.b64 %0, {%1, %1};" : "=l"(r) : "f"(w));
    return r;
}
__device__ __forceinline__ float2 unpack2(unsigned long long v) {
    float2 f;
    asm("mov.b64 {%0, %1}, %2;" : "=f"(f.x), "=f"(f.y) : "l"(v));
    return f;
}

// ============================================================================
// Stage 0: zero the histogram
// ============================================================================
__global__ void zero_kernel() {
    int i = blockIdx.x*blockDim.x + threadIdx.x;
    if (i < BB*NBINS/4) ((uint4*)g_hist)[i] = make_uint4(0u,0u,0u,0u);
}

// ============================================================================
// Stage 1: fused 1x1-conv heads (GEMM via packed FFMA2) + softmax + decode + hist
// ============================================================================
__global__ __launch_bounds__(NTHREADS, 2)
void head_kernel(const float* __restrict__ x,
                 const float* __restrict__ cls_w, const float* __restrict__ cls_b,
                 const float* __restrict__ reg_w, const float* __restrict__ reg_b,
                 const float* __restrict__ anchors)
{
    extern __shared__ float sm[];
    float* wT  = sm;                 // [256][66] transposed weights (union with esm)
    float* esm = sm;                 // [256][67] epilogue tile (reuses wT region)
    float* xsA = sm + WREGION;       // buffer 0: [CK][256]
    float* xsB = xsA + CHUNK_FLOATS; // buffer 1

    const int b    = blockIdx.y;
    const int hw0  = blockIdx.x * TILE_HW;
    const int tid  = threadIdx.x;
    const int lane = tid & 31;
    const int wrp  = tid >> 5;       // 0..10
    const int obase = wrp * OT;

    const float* xb = x + (size_t)b * CIN * HWTOT;
    const uint32_t xsA_s = (uint32_t)__cvta_generic_to_shared(xsA);
    const uint32_t xsB_s = (uint32_t)__cvta_generic_to_shared(xsB);

    // issue async copy of chunk cc into a buffer
    auto issue_chunk = [&](int cc, float* dst, uint32_t dst_s) {
        for (int idx = tid; idx < CHUNK_F4; idx += NTHREADS) {
            int c   = idx >> 6;          // /64
            int f4  = idx & 63;
            int col = f4 * 4;
            if (hw0 + col < HWTOT) {
                cp16(dst_s + (uint32_t)(c*TILE_HW + col)*4,
                     xb + (size_t)(cc + c)*HWTOT + hw0 + col);
            } else {
                *(float4*)(dst + c*TILE_HW + col) = make_float4(0.f,0.f,0.f,0.f);
            }
        }
        cp_commit();
    };

    // prefetch chunk 0 into buffer A
    issue_chunk(0, xsA, xsA_s);

    // load combined weights transposed into smem: wT[c*66 + o]
    for (int idx = tid; idx < NOUT*CIN; idx += NTHREADS) {
        int o = idx >> 8;            // /256
        int c = idx & 255;
        float v = (o < NCLS*AA) ? cls_w[o*CIN + c] : reg_w[(o - NCLS*AA)*CIN + c];
        wT[c*NOUT + o] = v;
    }

    unsigned long long acc[OT][NPAIR];
    #pragma unroll
    for (int j = 0; j < OT; j++)
        #pragma unroll
        for (int p = 0; p < NPAIR; p++) acc[j][p] = 0ull;

    #pragma unroll 1
    for (int it = 0; it < NITER; it++) {
        const int cc = it * CK;
        float* cur = (it & 1) ? xsB : xsA;
        if (it + 1 < NITER) {
            if (it > 0) __syncthreads();   // everyone done computing on the other buffer
            float*   nxt   = (it & 1) ? xsA : xsB;
            uint32_t nxt_s = (it & 1) ? xsA_s : xsB_s;
            issue_chunk(cc + CK, nxt, nxt_s);
            cp_wait<1>();                  // current chunk complete
        } else {
            cp_wait<0>();
        }
        __syncthreads();                   // cp.async data + wT (first iter) visible

        #pragma unroll
        for (int c = 0; c < CK; c++) {
            const float* wrow = &wT[(cc + c)*NOUT + obase];
            float2 w01 = *(const float2*)(wrow + 0);
            float2 w23 = *(const float2*)(wrow + 2);
            float2 w45 = *(const float2*)(wrow + 4);
            unsigned long long wp[OT];
            wp[0] = pack_dup(w01.x); wp[1] = pack_dup(w01.y);
            wp[2] = pack_dup(w23.x); wp[3] = pack_dup(w23.y);
            wp[4] = pack_dup(w45.x); wp[5] = pack_dup(w45.y);
            unsigned long long xp[NPAIR];
            #pragma unroll
            for (int p = 0; p < NPAIR; p++)
                xp[p] = *(const unsigned long long*)(cur + c*TILE_HW + 2*(lane + 32*p));
            #pragma unroll
            for (int j = 0; j < OT; j++)
                #pragma unroll
                for (int p = 0; p < NPAIR; p++)
                    ffma2(acc[j][p], wp[j], xp[p]);
        }
    }

    __syncthreads();   // done reading wT; reuse region as esm

    // add bias, scatter accumulators into epilogue tile esm[hw][o]
    float bias[OT];
    #pragma unroll
    for (int j = 0; j < OT; j++) {
        int o = obase + j;
        bias[j] = (o < NCLS*AA) ? cls_b[o] : reg_b[o - NCLS*AA];
    }
    #pragma unroll
    for (int j = 0; j < OT; j++)
        #pragma unroll
        for (int p = 0; p < NPAIR; p++) {
            float2 v = unpack2(acc[j][p]);
            int m0 = 2*(lane + 32*p);
            esm[(m0    )*ESM_STRIDE + obase + j] = v.x + bias[j];
            esm[(m0 + 1)*ESM_STRIDE + obase + j] = v.y + bias[j];
        }
    __syncthreads();

    // per-anchor epilogue: softmax + decode + store + warp-aggregated histogram
    for (int t = tid; t < TILE_HW*AA; t += NTHREADS) {
        int hwl = t / AA;
        int a   = t - hwl*AA;
        if (hw0 + hwl >= HWTOT) continue;
        int n = (hw0 + hwl)*AA + a;                 // anchor index within batch
        const float* e = esm + hwl*ESM_STRIDE;

        // softmax over 4 class logits (channel o = a*4 + c)
        float l0 = e[a*4+0], l1 = e[a*4+1], l2 = e[a*4+2], l3 = e[a*4+3];
        float m  = fmaxf(fmaxf(l0, l1), fmaxf(l2, l3));
        float e0 = expf(l0 - m), e1 = expf(l1 - m), e2 = expf(l2 - m), e3 = expf(l3 - m);
        float inv = 1.f / (e0 + e1 + e2 + e3);
        float p0 = e0*inv, p1 = e1*inv, p2 = e2*inv, p3 = e3*inv;

        size_t base = (size_t)b*NANCH + n;
        *(float4*)(g_scores + base*4) = make_float4(p0, p1, p2, p3);
        float mx = fmaxf(fmaxf(p1, p2), p3);
        g_maxs[base] = mx;

        // warp-aggregated histogram update
        unsigned bin  = __float_as_uint(mx) >> 16;
        unsigned amask = __activemask();
        unsigned peers = __match_any_sync(amask, bin);
        int leader = __ffs(peers) - 1;
        if ((tid & 31) == leader)
            atomicAdd(&g_hist[b*NBINS + bin], (unsigned)__popc(peers));

        // decode (channel o = 24 + a*7 + r); padded stride-8 vector stores
        const float* d  = e + NCLS*AA + a*NREG;
        const float* an = anchors + (size_t)n*NREG;
        float xa = an[0], ya = an[1], za = an[2];
        float dxa = an[3], dya = an[4], dza = an[5], ra = an[6];
        float diag = sqrtf(dxa*dxa + dya*dya);
        float* ob = g_boxes + base*BOXSTRIDE;
        float4 b0, b1;
        b0.x = fmaf(d[0], diag, xa);
        b0.y = fmaf(d[1], diag, ya);
        b0.z = fmaf(d[2], dza,  za);
        b0.w = expf(d[3]) * dxa;
        b1.x = expf(d[4]) * dya;
        b1.y = expf(d[5]) * dza;
        b1.z = d[6] + ra;
        b1.w = 0.f;
        *(float4*)(ob + 0) = b0;
        *(float4*)(ob + 4) = b1;
    }
}

// ============================================================================
// Stage 2: per-batch fused threshold-find + compact + sort + gather.
// ============================================================================
__global__ __launch_bounds__(1024)
void select_kernel(float* __restrict__ outS, float* __restrict__ outB)
{
    const int b   = blockIdx.x;
    const int tid = threadIdx.x;
    const int lane = tid & 31;
    const int wrp  = tid >> 5;

    __shared__ unsigned csum[1024];   // per-thread chunk sums (64 bins each)
    __shared__ unsigned wsum[32];     // per-warp sums (2048 bins each)
    __shared__ int      sThr;
    __shared__ int      sCnt;
    __shared__ float    sv[CANDMAX];
    __shared__ int      si[CANDMAX];

    // ---- phase 1: chunk sums of the 65536-bin histogram ----
    const unsigned* h = g_hist + b*NBINS;
    {
        const uint4* h4 = (const uint4*)(h + tid*64);
        unsigned s = 0;
        #pragma unroll
        for (int k = 0; k < 16; k++) { uint4 v = h4[k]; s += v.x + v.y + v.z + v.w; }
        csum[tid] = s;
        unsigned ws = s;
        #pragma unroll
        for (int o = 16; o > 0; o >>= 1) ws += __shfl_down_sync(0xFFFFFFFFu, ws, o);
        if (lane == 0) wsum[wrp] = ws;
    }
    if (tid == 0) sCnt = 0;
    __syncthreads();

    // ---- phase 2: hierarchical threshold find ----
    if (tid == 0) {
        unsigned cum = 0;
        int w = 31;
        for (; w > 0; w--) { if (cum + wsum[w] >= (unsigned)KTOP) break; cum += wsum[w]; }
        int t = w*32 + 31;
        for (; t > w*32; t--) { if (cum + csum[t] >= (unsigned)KTOP) break; cum += csum[t]; }
        int thr = t*64;
        for (int k = 63; k >= 0; k--) {
            unsigned c = h[t*64 + k];
            if (cum + c >= (unsigned)KTOP) { thr = t*64 + k; break; }
            cum += c;
        }
        sThr = thr;
    }
    __syncthreads();

    // ---- phase 3: compact candidates ----
    {
        const int thr = sThr;
        const float* mv = g_maxs + (size_t)b*NANCH;
        for (int i = tid; i < NANCH; i += 1024) {
            float v = mv[i];
            if ((int)(__float_as_uint(v) >> 16) >= thr) {
                int p = atomicAdd(&sCnt, 1);
                if (p < CANDMAX) { sv[p] = v; si[p] = i; }
            }
        }
    }
    __syncthreads();

    int cnt = sCnt;
    if (cnt > CANDMAX) cnt = CANDMAX;
    int p2 = 128;
    while (p2 < cnt) p2 <<= 1;
    for (int k = cnt + tid; k < p2; k += 1024) { sv[k] = -FLT_MAX; si[k] = 0x7FFFFFFF; }
    __syncthreads();

    // ---- phase 4: bitonic sort desc by (value, then ascending index) ----
    for (int k2 = 2; k2 <= p2; k2 <<= 1) {
        for (int j = k2 >> 1; j > 0; j >>= 1) {
            for (int i = tid; i < p2; i += 1024) {
                int ixj = i ^ j;
                if (ixj > i) {
                    float va = sv[i], vb = sv[ixj];
                    int   ia = si[i], ib = si[ixj];
                    bool a_below_b = (va < vb) || (va == vb && ia > ib);
                    bool up = ((i & k2) == 0);
                    if (up ? a_below_b : !a_below_b) {
                        sv[i] = vb; sv[ixj] = va; si[i] = ib; si[ixj] = ia;
                    }
                }
            }
            __syncthreads();
        }
    }

    // ---- phase 5: gather top-K ----
    if (tid < KTOP) {
        int k = tid;
        int n = si[k];
        size_t base = (size_t)b*NANCH + n;
        float4 s4 = *(const float4*)(g_scores + base*4);
        *(float4*)(outS + ((size_t)b*KTOP + k)*4) = s4;
        const float* bx = g_boxes + base*BOXSTRIDE;
        float4 b0 = *(const float4*)(bx + 0);
        float4 b1 = *(const float4*)(bx + 4);
        float* ob = outB + ((size_t)b*KTOP + k)*NREG;
        ob[0] = b0.x; ob[1] = b0.y; ob[2] = b0.z; ob[3] = b0.w;
        ob[4] = b1.x; ob[5] = b1.y; ob[6] = b1.z;
    }
}

// ============================================================================
extern "C" void kernel_launch(void* const* d_in, const int* in_sizes, int n_in,
                              void* d_out, int out_size)
{
    const float* x       = (const float*)d_in[0];
    const float* cls_w   = (const float*)d_in[1];
    const float* cls_b   = (const float*)d_in[2];
    const float* reg_w   = (const float*)d_in[3];
    const float* reg_b   = (const float*)d_in[4];
    const float* anchors = (const float*)d_in[5];

    float* outS = (float*)d_out;                 // [B, K, 4]
    float* outB = outS + (size_t)BB*KTOP*NCLS;   // [B, K, 7]

    cudaFuncSetAttribute(head_kernel, cudaFuncAttributeMaxDynamicSharedMemorySize, SMEM_BYTES);

    zero_kernel<<<(BB*NBINS/4 + 255)/256, 256>>>();
    head_kernel<<<dim3((HWTOT + TILE_HW - 1)/TILE_HW, BB), NTHREADS, SMEM_BYTES>>>(
        x, cls_w, cls_b, reg_w, reg_b, anchors);
    select_kernel<<<BB, 1024>>>(outS, outB);
}